// round 13
// baseline (speedup 1.0000x reference)
#include <cuda_runtime.h>
#include <cstdint>

// ---------------------------------------------------------------------------
// Problem constants
// ---------------------------------------------------------------------------
#define B_   32
#define LQ_  300
#define D_   256
#define H_   8
#define L_   3
#define P_   4
#define HD_  32
#define LV_  8400   // 80*80 + 40*40 + 20*20
#define NQF  320    // padded fused off|attn width (192 off + 96 attn + 32 pad)

// ---------------------------------------------------------------------------
// Packed fp32x2 helpers (Blackwell FFMA2 via PTX; exact fp32)
// ---------------------------------------------------------------------------
typedef unsigned long long u64;

__device__ __forceinline__ u64 pack2(float lo, float hi) {
    u64 r;
    asm("mov.b64 %0, {%1, %2};" : "=l"(r) : "r"(__float_as_uint(lo)), "r"(__float_as_uint(hi)));
    return r;
}
__device__ __forceinline__ void unpack2(u64 v, float& lo, float& hi) {
    unsigned ulo, uhi;
    asm("mov.b64 {%0, %1}, %2;" : "=r"(ulo), "=r"(uhi) : "l"(v));
    lo = __uint_as_float(ulo);
    hi = __uint_as_float(uhi);
}
__device__ __forceinline__ void ffma2(u64& d, u64 a, u64 b) {
    asm("fma.rn.f32x2 %0, %1, %2, %0;" : "+l"(d) : "l"(a), "l"(b));
}

// ---------------------------------------------------------------------------
// Scratch (device globals)
// ---------------------------------------------------------------------------
__device__ float g_qf  [(size_t)B_ * LQ_ * NQF];          // [9600,320]
__device__ float g_raw [(size_t)B_ * LQ_ * H_ * D_];      // [9600, 8, 256]
__device__ float g_wsum[(size_t)B_ * LQ_ * H_];           // [9600, 8]
__device__ float g_samp[(size_t)B_ * LQ_ * D_];           // [9600, 256]
__device__ float g_Wqf [256 * NQF];
__device__ float g_bqf [NQF];

// ---------------------------------------------------------------------------
// Build fused (padded) query-side weights: Wqf[256,320] = [Woff | Wattn | 0]
// ---------------------------------------------------------------------------
__global__ __launch_bounds__(256)
void prep_weights_kernel(const float* __restrict__ Woff, const float* __restrict__ boff,
                         const float* __restrict__ Wattn, const float* __restrict__ battn,
                         float* __restrict__ Wqf, float* __restrict__ bqf)
{
    int i = blockIdx.x * blockDim.x + threadIdx.x;
    if (i < 256 * NQF) {
        int k = i / NQF, j = i % NQF;
        float v = 0.f;
        if (j < 192)      v = Woff[k * 192 + j];
        else if (j < 288) v = Wattn[k * 96 + (j - 192)];
        Wqf[i] = v;
    }
    if (i < NQF) {
        float v = 0.f;
        if (i < 192)      v = boff[i];
        else if (i < 288) v = battn[i - 192];
        bqf[i] = v;
    }
}

// ---------------------------------------------------------------------------
// Tiled fp32 GEMM with FFMA2 (R8, proven): C[M,N] = A[M,K] @ W[K,N] + bias[N]
// BM=128, BN=64, BK=32; 256 threads; 8x4 micro-tile.
// ---------------------------------------------------------------------------
__global__ __launch_bounds__(256)
void gemm_bias128(const float* __restrict__ A, const float* __restrict__ W,
                  const float* __restrict__ bias, float* __restrict__ C,
                  int N, int K)
{
    __shared__ __align__(16) float As[32][132];
    __shared__ __align__(16) float Bs[32][64];

    const int tid = threadIdx.x;
    const int m0  = blockIdx.y * 128;
    const int n0  = blockIdx.x * 64;
    const int ty  = tid >> 4;
    const int tx  = tid & 15;

    const int am  = tid >> 3;
    const int akq = tid & 7;
    const int bk  = tid >> 4;
    const int bnq = tid & 15;

    u64 acc2[8][2];
#pragma unroll
    for (int i = 0; i < 8; i++) { acc2[i][0] = 0ull; acc2[i][1] = 0ull; }

    for (int k0 = 0; k0 < K; k0 += 32) {
#pragma unroll
        for (int t = 0; t < 4; t++) {
            int m = am + t * 32;
            float4 v = *(const float4*)(A + (size_t)(m0 + m) * K + k0 + akq * 4);
            As[akq * 4 + 0][m] = v.x;
            As[akq * 4 + 1][m] = v.y;
            As[akq * 4 + 2][m] = v.z;
            As[akq * 4 + 3][m] = v.w;
        }
#pragma unroll
        for (int t = 0; t < 2; t++) {
            int k = bk + t * 16;
            *(float4*)&Bs[k][bnq * 4] =
                *(const float4*)(W + (size_t)(k0 + k) * N + n0 + bnq * 4);
        }
        __syncthreads();

#pragma unroll
        for (int k = 0; k < 32; k++) {
            float4 a0 = *(const float4*)&As[k][ty * 8];
            float4 a1 = *(const float4*)&As[k][ty * 8 + 4];
            float4 b  = *(const float4*)&Bs[k][tx * 4];
            u64 b01 = pack2(b.x, b.y);
            u64 b23 = pack2(b.z, b.w);
            float av[8] = {a0.x, a0.y, a0.z, a0.w, a1.x, a1.y, a1.z, a1.w};
#pragma unroll
            for (int i = 0; i < 8; i++) {
                u64 ad = pack2(av[i], av[i]);
                ffma2(acc2[i][0], ad, b01);
                ffma2(acc2[i][1], ad, b23);
            }
        }
        __syncthreads();
    }

    float4 bb = *(const float4*)(bias + n0 + tx * 4);
#pragma unroll
    for (int i = 0; i < 8; i++) {
        int m = m0 + ty * 8 + i;
        float4 o;
        unpack2(acc2[i][0], o.x, o.y);
        unpack2(acc2[i][1], o.z, o.w);
        o.x += bb.x; o.y += bb.y; o.z += bb.z; o.w += bb.w;
        *(float4*)(C + (size_t)m * N + n0 + tx * 4) = o;
    }
}

// ---------------------------------------------------------------------------
// Sampling kernel (R8, at L1-byte floor). Warp <-> (bq, h).
// ---------------------------------------------------------------------------
__global__ __launch_bounds__(256)
void sample_raw_kernel(const float* __restrict__ rp,
                       const float* __restrict__ qf,     // [9600,320]
                       const float* __restrict__ value,  // [B, LV, 256]
                       float* __restrict__ raw,          // [9600, 8, 256]
                       float* __restrict__ wsumb)        // [9600, 8]
{
    const int bq   = blockIdx.x;
    const int h    = threadIdx.x >> 5;
    const int lane = threadIdx.x & 31;
    const int b    = bq / LQ_;

    const float4* vb = (const float4*)(value + (size_t)b * LV_ * D_);

    float logit = -1e30f;
    if (lane < 12)
        logit = qf[bq * NQF + 192 + h * 12 + lane];
    float mx = logit;
#pragma unroll
    for (int s = 16; s; s >>= 1) mx = fmaxf(mx, __shfl_xor_sync(0xffffffffu, mx, s));
    float e = (lane < 12) ? __expf(logit - mx) : 0.f;
    float ssum = e;
#pragma unroll
    for (int s = 16; s; s >>= 1) ssum += __shfl_xor_sync(0xffffffffu, ssum, s);
    const float aw = e / ssum;

    float cw0 = 0.f, cw1 = 0.f, cw2 = 0.f, cw3 = 0.f;
    int   i0 = 0, i1 = 0, i2 = 0, i3 = 0;
    float wsp = 0.f;

    if (lane < 12) {
        const int l  = lane >> 2;
        const int Wl = (l == 0) ? 80 : ((l == 1) ? 40 : 20);
        const int s0 = (l == 0) ? 0  : ((l == 1) ? 6400 : 8000);

        const float* rpp  = rp + bq * 12 + l * 4;
        const float cx = rpp[0], cy = rpp[1];
        const float hw = rpp[2] * 0.5f, hh = rpp[3] * 0.5f;

        const float* offp = qf + bq * NQF + h * 24 + lane * 2;
        const float lx = cx + offp[0] * hw;
        const float ly = cy + offp[1] * hh;

        const float fw = (float)Wl;
        const float x = lx * fw - 0.5f;
        const float y = ly * fw - 0.5f;
        const float x0f = floorf(x), y0f = floorf(y);
        const int   x0 = (int)x0f,  y0 = (int)y0f;
        const float wx1 = x - x0f, wx0 = 1.f - wx1;
        const float wy1 = y - y0f, wy0 = 1.f - wy1;

        const float fx0 = (x0 >= 0 && x0 < Wl)         ? 1.f : 0.f;
        const float fx1 = (x0 + 1 >= 0 && x0 + 1 < Wl) ? 1.f : 0.f;
        const float fy0 = (y0 >= 0 && y0 < Wl)         ? 1.f : 0.f;
        const float fy1 = (y0 + 1 >= 0 && y0 + 1 < Wl) ? 1.f : 0.f;

        const int xc0 = min(max(x0, 0), Wl - 1);
        const int xc1 = min(max(x0 + 1, 0), Wl - 1);
        const int yc0 = min(max(y0, 0), Wl - 1);
        const int yc1 = min(max(y0 + 1, 0), Wl - 1);

        cw0 = aw * wy0 * wx0 * fy0 * fx0;
        cw1 = aw * wy0 * wx1 * fy0 * fx1;
        cw2 = aw * wy1 * wx0 * fy1 * fx0;
        cw3 = aw * wy1 * wx1 * fy1 * fx1;
        wsp = cw0 + cw1 + cw2 + cw3;

        i0 = (s0 + yc0 * Wl + xc0) * 64;
        i1 = (s0 + yc0 * Wl + xc1) * 64;
        i2 = (s0 + yc1 * Wl + xc0) * 64;
        i3 = (s0 + yc1 * Wl + xc1) * 64;
    }

    float wsum = wsp;
#pragma unroll
    for (int s = 16; s; s >>= 1) wsum += __shfl_xor_sync(0xffffffffu, wsum, s);

    float4 a0 = make_float4(0.f, 0.f, 0.f, 0.f);
    float4 a1 = make_float4(0.f, 0.f, 0.f, 0.f);

#pragma unroll
    for (int p = 0; p < 12; p++) {
        const float c0 = __shfl_sync(0xffffffffu, cw0, p);
        const float c1 = __shfl_sync(0xffffffffu, cw1, p);
        const float c2 = __shfl_sync(0xffffffffu, cw2, p);
        const float c3 = __shfl_sync(0xffffffffu, cw3, p);
        const int   j0 = __shfl_sync(0xffffffffu, i0, p) + lane;
        const int   j1 = __shfl_sync(0xffffffffu, i1, p) + lane;
        const int   j2 = __shfl_sync(0xffffffffu, i2, p) + lane;
        const int   j3 = __shfl_sync(0xffffffffu, i3, p) + lane;

        float4 r0a = vb[j0], r0b = vb[j0 + 32];
        float4 r1a = vb[j1], r1b = vb[j1 + 32];
        float4 r2a = vb[j2], r2b = vb[j2 + 32];
        float4 r3a = vb[j3], r3b = vb[j3 + 32];

        a0.x += c0 * r0a.x; a0.y += c0 * r0a.y; a0.z += c0 * r0a.z; a0.w += c0 * r0a.w;
        a1.x += c0 * r0b.x; a1.y += c0 * r0b.y; a1.z += c0 * r0b.z; a1.w += c0 * r0b.w;
        a0.x += c1 * r1a.x; a0.y += c1 * r1a.y; a0.z += c1 * r1a.z; a0.w += c1 * r1a.w;
        a1.x += c1 * r1b.x; a1.y += c1 * r1b.y; a1.z += c1 * r1b.z; a1.w += c1 * r1b.w;
        a0.x += c2 * r2a.x; a0.y += c2 * r2a.y; a0.z += c2 * r2a.z; a0.w += c2 * r2a.w;
        a1.x += c2 * r2b.x; a1.y += c2 * r2b.y; a1.z += c2 * r2b.z; a1.w += c2 * r2b.w;
        a0.x += c3 * r3a.x; a0.y += c3 * r3a.y; a0.z += c3 * r3a.z; a0.w += c3 * r3a.w;
        a1.x += c3 * r3b.x; a1.y += c3 * r3b.y; a1.z += c3 * r3b.z; a1.w += c3 * r3b.w;
    }

    float4* rr = (float4*)(raw + ((size_t)bq * H_ + h) * D_);
    rr[lane]      = a0;
    rr[lane + 32] = a1;
    if (lane == 0) wsumb[(size_t)bq * H_ + h] = wsum;
}

// ---------------------------------------------------------------------------
// Per-head-PAIR projection, 256 threads, 4x8 thread tile (ratio 3.0 B/FFMA2).
// CTA = (m-tile 128 rows, head pair hp). Cols 0..31 -> head 2hp, 32..63 ->
// head 2hp+1. Thread: ty=tid>>3 (rows ty*4..+3), tx=tid&7 (cols tx*8..+7;
// all 8 cols in ONE head since tx*8 is 0,8,16,24 | 32,40,48,56).
// acc = 2 row-pairs x 8 cols = 16 u64 = 32 regs.
// ---------------------------------------------------------------------------
__global__ __launch_bounds__(256)
void proj_head_pair(const float* __restrict__ raw,    // [9600, 8, 256]
                    const float* __restrict__ wsumb,  // [9600, 8]
                    const float* __restrict__ Wv,     // [256, 256]
                    const float* __restrict__ bv,     // [256]
                    float* __restrict__ samp)         // [9600, 256]
{
    __shared__ __align__(16) float As0[32][132];   // head 2hp   [k][m]
    __shared__ __align__(16) float As1[32][132];   // head 2hp+1 [k][m]
    __shared__ __align__(16) float Bs[32][68];     // Wv cols hp*64..+63 [k][n]

    const int hp  = blockIdx.y;            // 0..3
    const int m0  = blockIdx.x * 128;
    const int tid = threadIdx.x;
    const int ty  = tid >> 3;               // 0..31 : rows ty*4 .. +3
    const int tx  = tid & 7;                // 0..7  : cols tx*8 .. +7

    const float* A0 = raw + ((size_t)m0 * H_ + 2 * hp)     * D_;   // row stride 2048
    const float* A1 = raw + ((size_t)m0 * H_ + 2 * hp + 1) * D_;
    const float* Bb = Wv + hp * 64;

    u64 acc2[2][8];   // [row-pair][col]
#pragma unroll
    for (int i = 0; i < 2; i++)
#pragma unroll
        for (int j = 0; j < 8; j++) acc2[i][j] = 0ull;

    float (*Asm)[132] = (tx < 4) ? As0 : As1;

    for (int k0 = 0; k0 < D_; k0 += 32) {
        // stage both A tiles: 1024 float4 each, 4/thread each
#pragma unroll
        for (int t = 0; t < 4; t++) {
            int idx = tid + t * 256;
            int row = idx >> 3, q = idx & 7;
            float4 v0 = *(const float4*)(A0 + (size_t)row * (H_ * D_) + k0 + q * 4);
            As0[q * 4 + 0][row] = v0.x;
            As0[q * 4 + 1][row] = v0.y;
            As0[q * 4 + 2][row] = v0.z;
            As0[q * 4 + 3][row] = v0.w;
            float4 v1 = *(const float4*)(A1 + (size_t)row * (H_ * D_) + k0 + q * 4);
            As1[q * 4 + 0][row] = v1.x;
            As1[q * 4 + 1][row] = v1.y;
            As1[q * 4 + 2][row] = v1.z;
            As1[q * 4 + 3][row] = v1.w;
        }
        // stage B: 32 k x 64 n = 512 float4, 2/thread
#pragma unroll
        for (int t = 0; t < 2; t++) {
            int idx = tid + t * 256;
            int k = idx >> 4, qn = idx & 15;
            *(float4*)&Bs[k][qn * 4] =
                *(const float4*)(Bb + (size_t)(k0 + k) * D_ + qn * 4);
        }
        __syncthreads();

#pragma unroll
        for (int k = 0; k < 32; k++) {
            float4 a = *(const float4*)&Asm[k][ty * 4];   // 4 rows, 16B
            u64 ap0 = pack2(a.x, a.y);                    // row pair (0,1)
            u64 ap1 = pack2(a.z, a.w);                    // row pair (2,3)
            float4 b0 = *(const float4*)&Bs[k][tx * 8];       // 16B
            float4 b1 = *(const float4*)&Bs[k][tx * 8 + 4];   // 16B
            u64 bd0 = pack2(b0.x, b0.x), bd1 = pack2(b0.y, b0.y);
            u64 bd2 = pack2(b0.z, b0.z), bd3 = pack2(b0.w, b0.w);
            u64 bd4 = pack2(b1.x, b1.x), bd5 = pack2(b1.y, b1.y);
            u64 bd6 = pack2(b1.z, b1.z), bd7 = pack2(b1.w, b1.w);
            ffma2(acc2[0][0], ap0, bd0); ffma2(acc2[0][1], ap0, bd1);
            ffma2(acc2[0][2], ap0, bd2); ffma2(acc2[0][3], ap0, bd3);
            ffma2(acc2[0][4], ap0, bd4); ffma2(acc2[0][5], ap0, bd5);
            ffma2(acc2[0][6], ap0, bd6); ffma2(acc2[0][7], ap0, bd7);
            ffma2(acc2[1][0], ap1, bd0); ffma2(acc2[1][1], ap1, bd1);
            ffma2(acc2[1][2], ap1, bd2); ffma2(acc2[1][3], ap1, bd3);
            ffma2(acc2[1][4], ap1, bd4); ffma2(acc2[1][5], ap1, bd5);
            ffma2(acc2[1][6], ap1, bd6); ffma2(acc2[1][7], ap1, bd7);
        }
        __syncthreads();
    }

    // epilogue: 4 rows x 8 cols; acc2[rp][j] = (row 2rp, row 2rp+1) for col j
    const int h = 2 * hp + (tx < 4 ? 0 : 1);
    float4 bb0 = *(const float4*)(bv + hp * 64 + tx * 8);
    float4 bb1 = *(const float4*)(bv + hp * 64 + tx * 8 + 4);
    const float bbv[8] = {bb0.x, bb0.y, bb0.z, bb0.w, bb1.x, bb1.y, bb1.z, bb1.w};

#pragma unroll
    for (int rp = 0; rp < 2; rp++) {
        float r0[8], r1[8];
#pragma unroll
        for (int j = 0; j < 8; j++) unpack2(acc2[rp][j], r0[j], r1[j]);
        int row0 = m0 + ty * 4 + 2 * rp;
        float ws0 = wsumb[(size_t)row0 * H_ + h];
        float ws1 = wsumb[(size_t)(row0 + 1) * H_ + h];
        float* c0 = samp + (size_t)row0 * D_ + hp * 64 + tx * 8;
        float* c1 = c0 + D_;
        *(float4*)c0       = make_float4(r0[0]+ws0*bbv[0], r0[1]+ws0*bbv[1], r0[2]+ws0*bbv[2], r0[3]+ws0*bbv[3]);
        *(float4*)(c0 + 4) = make_float4(r0[4]+ws0*bbv[4], r0[5]+ws0*bbv[5], r0[6]+ws0*bbv[6], r0[7]+ws0*bbv[7]);
        *(float4*)c1       = make_float4(r1[0]+ws1*bbv[0], r1[1]+ws1*bbv[1], r1[2]+ws1*bbv[2], r1[3]+ws1*bbv[3]);
        *(float4*)(c1 + 4) = make_float4(r1[4]+ws1*bbv[4], r1[5]+ws1*bbv[5], r1[6]+ws1*bbv[6], r1[7]+ws1*bbv[7]);
    }
}

// ---------------------------------------------------------------------------
// Launch
// ---------------------------------------------------------------------------
extern "C" void kernel_launch(void* const* d_in, const int* in_sizes, int n_in,
                              void* d_out, int out_size)
{
    const float* query = (const float*)d_in[0];
    const float* rp    = (const float*)d_in[1];
    const float* value = (const float*)d_in[2];
    const float* Wv    = (const float*)d_in[5];
    const float* bv    = (const float*)d_in[6];
    const float* Woff  = (const float*)d_in[7];
    const float* boff  = (const float*)d_in[8];
    const float* Wattn = (const float*)d_in[9];
    const float* battn = (const float*)d_in[10];
    const float* Wout  = (const float*)d_in[11];
    const float* bout  = (const float*)d_in[12];
    float* out = (float*)d_out;

    float *qfb, *rawb, *wsumb, *samp, *Wqf, *bqf;
    cudaGetSymbolAddress((void**)&qfb,   g_qf);
    cudaGetSymbolAddress((void**)&rawb,  g_raw);
    cudaGetSymbolAddress((void**)&wsumb, g_wsum);
    cudaGetSymbolAddress((void**)&samp,  g_samp);
    cudaGetSymbolAddress((void**)&Wqf,   g_Wqf);
    cudaGetSymbolAddress((void**)&bqf,   g_bqf);

    const int Mq = B_ * LQ_;     // 9600 = 75 * 128

    // 0) fused padded query-side weights
    prep_weights_kernel<<<(256 * NQF + 255) / 256, 256>>>(Woff, boff, Wattn, battn, Wqf, bqf);

    // 1) fused offsets+attn: [9600,256] @ [256,320]
    gemm_bias128<<<dim3(NQF / 64, Mq / 128), 256>>>(query, Wqf, bqf, qfb, NQF, D_);

    // 2) gather-only sampler -> raw [9600,8,256], wsum [9600,8]
    sample_raw_kernel<<<Mq, 256>>>(rp, qfb, value, rawb, wsumb);

    // 3) per-head-pair projection -> samp [9600,256]
    proj_head_pair<<<dim3(Mq / 128, H_ / 2), 256>>>(rawb, wsumb, Wv, bv, samp);

    // 4) output projection: [9600,256] @ [256,256]
    gemm_bias128<<<dim3(D_ / 64, Mq / 128), 256>>>(samp, Wout, bout, out, D_, D_);
}

// round 14
// speedup vs baseline: 1.1240x; 1.1240x over previous
#include <cuda_runtime.h>
#include <cstdint>

// ---------------------------------------------------------------------------
// Problem constants
// ---------------------------------------------------------------------------
#define B_   32
#define LQ_  300
#define D_   256
#define H_   8
#define L_   3
#define P_   4
#define HD_  32
#define LV_  8400   // 80*80 + 40*40 + 20*20
#define NQF  320    // padded fused off|attn width (192 off + 96 attn + 32 pad)

// ---------------------------------------------------------------------------
// Packed fp32x2 helpers (Blackwell FFMA2 via PTX; exact fp32)
// ---------------------------------------------------------------------------
typedef unsigned long long u64;

__device__ __forceinline__ u64 pack2(float lo, float hi) {
    u64 r;
    asm("mov.b64 %0, {%1, %2};" : "=l"(r) : "r"(__float_as_uint(lo)), "r"(__float_as_uint(hi)));
    return r;
}
__device__ __forceinline__ void unpack2(u64 v, float& lo, float& hi) {
    unsigned ulo, uhi;
    asm("mov.b64 {%0, %1}, %2;" : "=r"(ulo), "=r"(uhi) : "l"(v));
    lo = __uint_as_float(ulo);
    hi = __uint_as_float(uhi);
}
__device__ __forceinline__ void ffma2(u64& d, u64 a, u64 b) {
    asm("fma.rn.f32x2 %0, %1, %2, %0;" : "+l"(d) : "l"(a), "l"(b));
}

// ---------------------------------------------------------------------------
// Scratch (device globals)
// ---------------------------------------------------------------------------
__device__ float g_qf  [(size_t)B_ * LQ_ * NQF];          // [9600,320]
__device__ float g_raw [(size_t)B_ * LQ_ * H_ * D_];      // [9600, 8, 256]
__device__ float g_wsum[(size_t)B_ * LQ_ * H_];           // [9600, 8]
__device__ float g_samp[(size_t)B_ * LQ_ * D_];           // [9600, 256]
__device__ float g_Wqf [256 * NQF];
__device__ float g_bqf [NQF];

// ---------------------------------------------------------------------------
// Build fused (padded) query-side weights: Wqf[256,320] = [Woff | Wattn | 0]
// ---------------------------------------------------------------------------
__global__ __launch_bounds__(256)
void prep_weights_kernel(const float* __restrict__ Woff, const float* __restrict__ boff,
                         const float* __restrict__ Wattn, const float* __restrict__ battn,
                         float* __restrict__ Wqf, float* __restrict__ bqf)
{
    int i = blockIdx.x * blockDim.x + threadIdx.x;
    if (i < 256 * NQF) {
        int k = i / NQF, j = i % NQF;
        float v = 0.f;
        if (j < 192)      v = Woff[k * 192 + j];
        else if (j < 288) v = Wattn[k * 96 + (j - 192)];
        Wqf[i] = v;
    }
    if (i < NQF) {
        float v = 0.f;
        if (i < 192)      v = boff[i];
        else if (i < 288) v = battn[i - 192];
        bqf[i] = v;
    }
}

// ---------------------------------------------------------------------------
// Tiled fp32 GEMM with FFMA2 (R8, proven): C[M,N] = A[M,K] @ W[K,N] + bias[N]
// BM=128, BN=64, BK=32; 256 threads; 8x4 micro-tile.
// ---------------------------------------------------------------------------
__global__ __launch_bounds__(256)
void gemm_bias128(const float* __restrict__ A, const float* __restrict__ W,
                  const float* __restrict__ bias, float* __restrict__ C,
                  int N, int K)
{
    __shared__ __align__(16) float As[32][132];
    __shared__ __align__(16) float Bs[32][64];

    const int tid = threadIdx.x;
    const int m0  = blockIdx.y * 128;
    const int n0  = blockIdx.x * 64;
    const int ty  = tid >> 4;
    const int tx  = tid & 15;

    const int am  = tid >> 3;
    const int akq = tid & 7;
    const int bk  = tid >> 4;
    const int bnq = tid & 15;

    u64 acc2[8][2];
#pragma unroll
    for (int i = 0; i < 8; i++) { acc2[i][0] = 0ull; acc2[i][1] = 0ull; }

    for (int k0 = 0; k0 < K; k0 += 32) {
#pragma unroll
        for (int t = 0; t < 4; t++) {
            int m = am + t * 32;
            float4 v = *(const float4*)(A + (size_t)(m0 + m) * K + k0 + akq * 4);
            As[akq * 4 + 0][m] = v.x;
            As[akq * 4 + 1][m] = v.y;
            As[akq * 4 + 2][m] = v.z;
            As[akq * 4 + 3][m] = v.w;
        }
#pragma unroll
        for (int t = 0; t < 2; t++) {
            int k = bk + t * 16;
            *(float4*)&Bs[k][bnq * 4] =
                *(const float4*)(W + (size_t)(k0 + k) * N + n0 + bnq * 4);
        }
        __syncthreads();

#pragma unroll
        for (int k = 0; k < 32; k++) {
            float4 a0 = *(const float4*)&As[k][ty * 8];
            float4 a1 = *(const float4*)&As[k][ty * 8 + 4];
            float4 b  = *(const float4*)&Bs[k][tx * 4];
            u64 b01 = pack2(b.x, b.y);
            u64 b23 = pack2(b.z, b.w);
            float av[8] = {a0.x, a0.y, a0.z, a0.w, a1.x, a1.y, a1.z, a1.w};
#pragma unroll
            for (int i = 0; i < 8; i++) {
                u64 ad = pack2(av[i], av[i]);
                ffma2(acc2[i][0], ad, b01);
                ffma2(acc2[i][1], ad, b23);
            }
        }
        __syncthreads();
    }

    float4 bb = *(const float4*)(bias + n0 + tx * 4);
#pragma unroll
    for (int i = 0; i < 8; i++) {
        int m = m0 + ty * 8 + i;
        float4 o;
        unpack2(acc2[i][0], o.x, o.y);
        unpack2(acc2[i][1], o.z, o.w);
        o.x += bb.x; o.y += bb.y; o.z += bb.z; o.w += bb.w;
        *(float4*)(C + (size_t)m * N + n0 + tx * 4) = o;
    }
}

// ---------------------------------------------------------------------------
// Sampling kernel (R8, at L1-byte floor). Warp <-> (bq, h).
// ---------------------------------------------------------------------------
__global__ __launch_bounds__(256)
void sample_raw_kernel(const float* __restrict__ rp,
                       const float* __restrict__ qf,     // [9600,320]
                       const float* __restrict__ value,  // [B, LV, 256]
                       float* __restrict__ raw,          // [9600, 8, 256]
                       float* __restrict__ wsumb)        // [9600, 8]
{
    const int bq   = blockIdx.x;
    const int h    = threadIdx.x >> 5;
    const int lane = threadIdx.x & 31;
    const int b    = bq / LQ_;

    const float4* vb = (const float4*)(value + (size_t)b * LV_ * D_);

    float logit = -1e30f;
    if (lane < 12)
        logit = qf[bq * NQF + 192 + h * 12 + lane];
    float mx = logit;
#pragma unroll
    for (int s = 16; s; s >>= 1) mx = fmaxf(mx, __shfl_xor_sync(0xffffffffu, mx, s));
    float e = (lane < 12) ? __expf(logit - mx) : 0.f;
    float ssum = e;
#pragma unroll
    for (int s = 16; s; s >>= 1) ssum += __shfl_xor_sync(0xffffffffu, ssum, s);
    const float aw = e / ssum;

    float cw0 = 0.f, cw1 = 0.f, cw2 = 0.f, cw3 = 0.f;
    int   i0 = 0, i1 = 0, i2 = 0, i3 = 0;
    float wsp = 0.f;

    if (lane < 12) {
        const int l  = lane >> 2;
        const int Wl = (l == 0) ? 80 : ((l == 1) ? 40 : 20);
        const int s0 = (l == 0) ? 0  : ((l == 1) ? 6400 : 8000);

        const float* rpp  = rp + bq * 12 + l * 4;
        const float cx = rpp[0], cy = rpp[1];
        const float hw = rpp[2] * 0.5f, hh = rpp[3] * 0.5f;

        const float* offp = qf + bq * NQF + h * 24 + lane * 2;
        const float lx = cx + offp[0] * hw;
        const float ly = cy + offp[1] * hh;

        const float fw = (float)Wl;
        const float x = lx * fw - 0.5f;
        const float y = ly * fw - 0.5f;
        const float x0f = floorf(x), y0f = floorf(y);
        const int   x0 = (int)x0f,  y0 = (int)y0f;
        const float wx1 = x - x0f, wx0 = 1.f - wx1;
        const float wy1 = y - y0f, wy0 = 1.f - wy1;

        const float fx0 = (x0 >= 0 && x0 < Wl)         ? 1.f : 0.f;
        const float fx1 = (x0 + 1 >= 0 && x0 + 1 < Wl) ? 1.f : 0.f;
        const float fy0 = (y0 >= 0 && y0 < Wl)         ? 1.f : 0.f;
        const float fy1 = (y0 + 1 >= 0 && y0 + 1 < Wl) ? 1.f : 0.f;

        const int xc0 = min(max(x0, 0), Wl - 1);
        const int xc1 = min(max(x0 + 1, 0), Wl - 1);
        const int yc0 = min(max(y0, 0), Wl - 1);
        const int yc1 = min(max(y0 + 1, 0), Wl - 1);

        cw0 = aw * wy0 * wx0 * fy0 * fx0;
        cw1 = aw * wy0 * wx1 * fy0 * fx1;
        cw2 = aw * wy1 * wx0 * fy1 * fx0;
        cw3 = aw * wy1 * wx1 * fy1 * fx1;
        wsp = cw0 + cw1 + cw2 + cw3;

        i0 = (s0 + yc0 * Wl + xc0) * 64;
        i1 = (s0 + yc0 * Wl + xc1) * 64;
        i2 = (s0 + yc1 * Wl + xc0) * 64;
        i3 = (s0 + yc1 * Wl + xc1) * 64;
    }

    float wsum = wsp;
#pragma unroll
    for (int s = 16; s; s >>= 1) wsum += __shfl_xor_sync(0xffffffffu, wsum, s);

    float4 a0 = make_float4(0.f, 0.f, 0.f, 0.f);
    float4 a1 = make_float4(0.f, 0.f, 0.f, 0.f);

#pragma unroll
    for (int p = 0; p < 12; p++) {
        const float c0 = __shfl_sync(0xffffffffu, cw0, p);
        const float c1 = __shfl_sync(0xffffffffu, cw1, p);
        const float c2 = __shfl_sync(0xffffffffu, cw2, p);
        const float c3 = __shfl_sync(0xffffffffu, cw3, p);
        const int   j0 = __shfl_sync(0xffffffffu, i0, p) + lane;
        const int   j1 = __shfl_sync(0xffffffffu, i1, p) + lane;
        const int   j2 = __shfl_sync(0xffffffffu, i2, p) + lane;
        const int   j3 = __shfl_sync(0xffffffffu, i3, p) + lane;

        float4 r0a = vb[j0], r0b = vb[j0 + 32];
        float4 r1a = vb[j1], r1b = vb[j1 + 32];
        float4 r2a = vb[j2], r2b = vb[j2 + 32];
        float4 r3a = vb[j3], r3b = vb[j3 + 32];

        a0.x += c0 * r0a.x; a0.y += c0 * r0a.y; a0.z += c0 * r0a.z; a0.w += c0 * r0a.w;
        a1.x += c0 * r0b.x; a1.y += c0 * r0b.y; a1.z += c0 * r0b.z; a1.w += c0 * r0b.w;
        a0.x += c1 * r1a.x; a0.y += c1 * r1a.y; a0.z += c1 * r1a.z; a0.w += c1 * r1a.w;
        a1.x += c1 * r1b.x; a1.y += c1 * r1b.y; a1.z += c1 * r1b.z; a1.w += c1 * r1b.w;
        a0.x += c2 * r2a.x; a0.y += c2 * r2a.y; a0.z += c2 * r2a.z; a0.w += c2 * r2a.w;
        a1.x += c2 * r2b.x; a1.y += c2 * r2b.y; a1.z += c2 * r2b.z; a1.w += c2 * r2b.w;
        a0.x += c3 * r3a.x; a0.y += c3 * r3a.y; a0.z += c3 * r3a.z; a0.w += c3 * r3a.w;
        a1.x += c3 * r3b.x; a1.y += c3 * r3b.y; a1.z += c3 * r3b.z; a1.w += c3 * r3b.w;
    }

    float4* rr = (float4*)(raw + ((size_t)bq * H_ + h) * D_);
    rr[lane]      = a0;
    rr[lane + 32] = a1;
    if (lane == 0) wsumb[(size_t)bq * H_ + h] = wsum;
}

// ---------------------------------------------------------------------------
// Per-head block-diagonal projection, 128 threads, 8-row x 4-col thread tile.
// Same BM=128 / BN=32 / BK=32 / 21KB smem / grid 600 as R8 (occupancy-safe);
// only the thread tile changes: 48 B LDS per thread-k for 16 FFMA2
// (3.0 B/FFMA2 vs R8's 4.0). acc = 4 row-pair u64 x 4 cols = 32 regs.
// Per-output k-summation order identical to R8 -> bitwise-same result.
// ---------------------------------------------------------------------------
__global__ __launch_bounds__(128)
void proj_head_kernel(const float* __restrict__ raw,    // [9600, 8, 256]
                      const float* __restrict__ wsumb,  // [9600, 8]
                      const float* __restrict__ Wv,     // [256, 256]
                      const float* __restrict__ bv,     // [256]
                      float* __restrict__ samp)         // [9600, 256]
{
    __shared__ __align__(16) float As[32][132];   // [k][m]
    __shared__ __align__(16) float Bs[32][32];    // [k][n]

    const int h   = blockIdx.y;
    const int m0  = blockIdx.x * 128;
    const int tid = threadIdx.x;
    const int ty  = tid >> 3;    // 0..15 : rows ty*8 .. +7
    const int tx  = tid & 7;     // 0..7  : cols tx*4 .. +3

    u64 acc2[4][4];   // [row-pair][col]
#pragma unroll
    for (int i = 0; i < 4; i++)
#pragma unroll
        for (int j = 0; j < 4; j++) acc2[i][j] = 0ull;

    const float* Ab = raw + ((size_t)m0 * H_ + h) * D_;   // row stride 2048
    const float* Bb = Wv + h * HD_;

    for (int k0 = 0; k0 < D_; k0 += 32) {
        // stage A 128x32: 1024 float4, 8 per thread (transpose to As[k][m])
#pragma unroll
        for (int t = 0; t < 8; t++) {
            int idx = tid + t * 128;
            int m = idx >> 3, q = idx & 7;
            float4 v = *(const float4*)(Ab + (size_t)m * (H_ * D_) + k0 + q * 4);
            As[q * 4 + 0][m] = v.x;
            As[q * 4 + 1][m] = v.y;
            As[q * 4 + 2][m] = v.z;
            As[q * 4 + 3][m] = v.w;
        }
        // stage B 32x32: 256 float4, 2 per thread
#pragma unroll
        for (int t = 0; t < 2; t++) {
            int idx = tid + t * 128;
            int k = idx >> 3, qn = idx & 7;
            *(float4*)&Bs[k][qn * 4] =
                *(const float4*)(Bb + (size_t)(k0 + k) * D_ + qn * 4);
        }
        __syncthreads();

#pragma unroll
        for (int k = 0; k < 32; k++) {
            float4 a01 = *(const float4*)&As[k][ty * 8];      // rows 8ty..+3
            float4 a23 = *(const float4*)&As[k][ty * 8 + 4];  // rows 8ty+4..+7
            u64 ap0 = pack2(a01.x, a01.y);    // rows (8ty+0, 8ty+1)
            u64 ap1 = pack2(a01.z, a01.w);    // rows (8ty+2, 8ty+3)
            u64 ap2 = pack2(a23.x, a23.y);    // rows (8ty+4, 8ty+5)
            u64 ap3 = pack2(a23.z, a23.w);    // rows (8ty+6, 8ty+7)
            float4 b = *(const float4*)&Bs[k][tx * 4];
            u64 bd0 = pack2(b.x, b.x);
            u64 bd1 = pack2(b.y, b.y);
            u64 bd2 = pack2(b.z, b.z);
            u64 bd3 = pack2(b.w, b.w);
            ffma2(acc2[0][0], ap0, bd0); ffma2(acc2[0][1], ap0, bd1);
            ffma2(acc2[0][2], ap0, bd2); ffma2(acc2[0][3], ap0, bd3);
            ffma2(acc2[1][0], ap1, bd0); ffma2(acc2[1][1], ap1, bd1);
            ffma2(acc2[1][2], ap1, bd2); ffma2(acc2[1][3], ap1, bd3);
            ffma2(acc2[2][0], ap2, bd0); ffma2(acc2[2][1], ap2, bd1);
            ffma2(acc2[2][2], ap2, bd2); ffma2(acc2[2][3], ap2, bd3);
            ffma2(acc2[3][0], ap3, bd0); ffma2(acc2[3][1], ap3, bd1);
            ffma2(acc2[3][2], ap3, bd2); ffma2(acc2[3][3], ap3, bd3);
        }
        __syncthreads();
    }

    // epilogue: acc2[rp][j] = (row 8ty+2rp, row 8ty+2rp+1) for col tx*4+j
    float4 bvv = *(const float4*)(bv + h * HD_ + tx * 4);
#pragma unroll
    for (int rp = 0; rp < 4; rp++) {
        float r0[4], r1[4];
#pragma unroll
        for (int j = 0; j < 4; j++) unpack2(acc2[rp][j], r0[j], r1[j]);
        int row0 = m0 + ty * 8 + 2 * rp;
        float ws0 = wsumb[(size_t)row0 * H_ + h];
        float ws1 = wsumb[(size_t)(row0 + 1) * H_ + h];
        float* c0 = samp + (size_t)row0 * D_ + h * HD_ + tx * 4;
        float* c1 = c0 + D_;
        *(float4*)c0 = make_float4(r0[0] + ws0 * bvv.x, r0[1] + ws0 * bvv.y,
                                   r0[2] + ws0 * bvv.z, r0[3] + ws0 * bvv.w);
        *(float4*)c1 = make_float4(r1[0] + ws1 * bvv.x, r1[1] + ws1 * bvv.y,
                                   r1[2] + ws1 * bvv.z, r1[3] + ws1 * bvv.w);
    }
}

// ---------------------------------------------------------------------------
// Launch
// ---------------------------------------------------------------------------
extern "C" void kernel_launch(void* const* d_in, const int* in_sizes, int n_in,
                              void* d_out, int out_size)
{
    const float* query = (const float*)d_in[0];
    const float* rp    = (const float*)d_in[1];
    const float* value = (const float*)d_in[2];
    const float* Wv    = (const float*)d_in[5];
    const float* bv    = (const float*)d_in[6];
    const float* Woff  = (const float*)d_in[7];
    const float* boff  = (const float*)d_in[8];
    const float* Wattn = (const float*)d_in[9];
    const float* battn = (const float*)d_in[10];
    const float* Wout  = (const float*)d_in[11];
    const float* bout  = (const float*)d_in[12];
    float* out = (float*)d_out;

    float *qfb, *rawb, *wsumb, *samp, *Wqf, *bqf;
    cudaGetSymbolAddress((void**)&qfb,   g_qf);
    cudaGetSymbolAddress((void**)&rawb,  g_raw);
    cudaGetSymbolAddress((void**)&wsumb, g_wsum);
    cudaGetSymbolAddress((void**)&samp,  g_samp);
    cudaGetSymbolAddress((void**)&Wqf,   g_Wqf);
    cudaGetSymbolAddress((void**)&bqf,   g_bqf);

    const int Mq = B_ * LQ_;     // 9600 = 75 * 128

    // 0) fused padded query-side weights
    prep_weights_kernel<<<(256 * NQF + 255) / 256, 256>>>(Woff, boff, Wattn, battn, Wqf, bqf);

    // 1) fused offsets+attn: [9600,256] @ [256,320]
    gemm_bias128<<<dim3(NQF / 64, Mq / 128), 256>>>(query, Wqf, bqf, qfb, NQF, D_);

    // 2) gather-only sampler -> raw [9600,8,256], wsum [9600,8]
    sample_raw_kernel<<<Mq, 256>>>(rp, qfb, value, rawb, wsumb);

    // 3) per-head projection -> samp [9600,256]
    proj_head_kernel<<<dim3(Mq / 128, H_), 128>>>(rawb, wsumb, Wv, bv, samp);

    // 4) output projection: [9600,256] @ [256,256]
    gemm_bias128<<<dim3(D_ / 64, Mq / 128), 256>>>(samp, Wout, bout, out, D_, D_);
}